// round 11
// baseline (speedup 1.0000x reference)
#include <cuda_runtime.h>
#include <math.h>
#include <stdint.h>

#define EMAX 800000
#define NMAX 50000

// ---------------- scratch ----------------------------------------------------
__device__ float g_logits[EMAX * 4];   // logits, then overwritten with ex
__device__ float g_segmax[NMAX * 4];
__device__ float g_segsum[NMAX * 4];
__device__ float g_agg[NMAX * 128];
__device__ float g_hvw[NMAX * 256];    // hV @ Wm1[:, :128]^T  per node
// pre-rounded tf32 weights: Wm1(98304) Wm2(32768) Wv1(32768) Wv2(16384) Wv3(16384)
__device__ __align__(16) float g_w[196608];

// ---------------- helpers ------------------------------------------------------
__device__ __forceinline__ void fma2(unsigned long long& acc, unsigned long long a,
                                     unsigned long long b) {
    asm("fma.rn.f32x2 %0, %1, %2, %0;" : "+l"(acc) : "l"(a), "l"(b));
}
__device__ __forceinline__ float f2sum(unsigned long long a) {
    float lo, hi;
    asm("mov.b64 {%0,%1}, %2;" : "=f"(lo), "=f"(hi) : "l"(a));
    return lo + hi;
}
__device__ __forceinline__ float gelu_f(float x) {
    return 0.5f * x * (1.0f + erff(x * 0.7071067811865476f));
}
__device__ __forceinline__ void red4(float* p, float4 v) {
    asm volatile("red.global.add.v4.f32 [%0], {%1,%2,%3,%4};"
                 :: "l"(p), "f"(v.x), "f"(v.y), "f"(v.z), "f"(v.w) : "memory");
}
__device__ __forceinline__ void atomicMaxF(float* a, float v) {
    if (v >= 0.0f) atomicMax((int*)a, __float_as_int(v));
    else           atomicMin((unsigned int*)a, __float_as_uint(v));
}
__device__ __forceinline__ uint32_t tf32r(float f) {
    uint32_t r;
    asm("cvt.rna.tf32.f32 %0, %1;" : "=r"(r) : "f"(f));
    return r;
}
__device__ __forceinline__ uint32_t smem_u32(const void* p) {
    uint32_t a;
    asm("{ .reg .u64 t; cvta.to.shared.u64 t, %1; cvt.u32.u64 %0, t; }"
        : "=r"(a) : "l"(p));
    return a;
}
__device__ __forceinline__ void cp16(uint32_t dst, const void* src) {
    asm volatile("cp.async.ca.shared.global [%0], [%1], 16;" :: "r"(dst), "l"(src));
}
#define CP_COMMIT() asm volatile("cp.async.commit_group;" ::: "memory")
#define CP_WAIT0()  asm volatile("cp.async.wait_group 0;" ::: "memory")

// Warp MMA, 2 m-tiles (M32) x NT n-tiles. A[m][k] pitch ap u32 (tf32 bits);
// B[n][k] pitch bp u32. D covers rows [m0,m0+32), cols [n0, n0+8*NT).
template<int NT>
__device__ __forceinline__ void mma_block2(
    const uint32_t* __restrict__ A, int ap, int ka,
    const uint32_t* __restrict__ B, int bp, int kb,
    int m0, int n0, int ksteps, float d[2][NT][4], int g, int c)
{
    for (int ks = 0; ks < ksteps; ks++) {
        uint32_t a[2][4];
#pragma unroll
        for (int mi = 0; mi < 2; mi++) {
            const uint32_t* Ar = A + (m0 + mi * 16 + g) * ap + ka + ks * 8 + c;
            a[mi][0] = Ar[0];
            a[mi][2] = Ar[4];
            a[mi][1] = Ar[8 * ap];
            a[mi][3] = Ar[8 * ap + 4];
        }
        const uint32_t* Bb = B + kb + ks * 8 + c + (n0 + g) * bp;
#pragma unroll
        for (int nt = 0; nt < NT; nt++) {
            uint32_t b0 = Bb[nt * 8 * bp];
            uint32_t b1 = Bb[nt * 8 * bp + 4];
#pragma unroll
            for (int mi = 0; mi < 2; mi++) {
                asm volatile(
                    "mma.sync.aligned.m16n8k8.row.col.f32.tf32.tf32.f32 "
                    "{%0,%1,%2,%3}, {%4,%5,%6,%7}, {%8,%9}, {%0,%1,%2,%3};"
                    : "+f"(d[mi][nt][0]), "+f"(d[mi][nt][1]),
                      "+f"(d[mi][nt][2]), "+f"(d[mi][nt][3])
                    : "r"(a[mi][0]), "r"(a[mi][1]), "r"(a[mi][2]), "r"(a[mi][3]),
                      "r"(b0), "r"(b1));
            }
        }
    }
}

// ---------------- init / weight prep ------------------------------------------
__global__ void k_init(int N) {
    int i = blockIdx.x * blockDim.x + threadIdx.x;
    if (i < N * 128) g_agg[i] = 0.0f;
    if (i < N * 4) {
        g_segmax[i] = __int_as_float(0xff800000);
        g_segsum[i] = 0.0f;
    }
}

__global__ void k_prep(const float* __restrict__ Wm1, const float* __restrict__ Wm2,
                       const float* __restrict__ Wv1, const float* __restrict__ Wv2,
                       const float* __restrict__ Wv3) {
    int i = blockIdx.x * 256 + threadIdx.x;
    float v;
    if (i < 98304)       v = Wm1[i];
    else if (i < 131072) v = Wm2[i - 98304];
    else if (i < 163840) v = Wv1[i - 131072];
    else if (i < 180224) v = Wv2[i - 163840];
    else                 v = Wv3[i - 180224];
    g_w[i] = __uint_as_float(tf32r(v));
}

// =====================================================================
// K0: g_hvw[n][0..255] = hV[n] @ Wm1[:, :128]^T   (tf32 mma)
// =====================================================================
#define HV_SMEM (27648 * 4)

__global__ void __launch_bounds__(512, 1) k_hvw(const float* __restrict__ hV, int N)
{
    extern __shared__ uint32_t sm[];
    const int tid = threadIdx.x;
    const int w = tid >> 5, lane = tid & 31;
    const int g = lane >> 2, c = lane & 3;
    const int bb = blockIdx.x * 128;
    const uint32_t sb = smem_u32(sm);
    const float* gWm1 = g_w;

    auto issue = [&](int ch, int hsOff, int wsOff) {
#pragma unroll
        for (int rep = 0; rep < 2; rep++) {
            int it = rep * 512 + tid;
            int e = it >> 3, q = it & 7;
            cp16(sb + (hsOff + e * 36 + q * 4) * 4,
                 hV + (size_t)min(bb + e, N - 1) * 128 + ch * 32 + q * 4);
        }
#pragma unroll
        for (int rep = 0; rep < 4; rep++) {
            int it = rep * 512 + tid;
            int o = it >> 3, q = it & 7;
            cp16(sb + (wsOff + o * 36 + q * 4) * 4,
                 gWm1 + (size_t)o * 384 + ch * 32 + q * 4);
        }
        CP_COMMIT();
    };

    issue(0, 0, 9216);

    const int m0 = (w >> 2) * 32;
    const int n1 = (w & 3) * 64;
    float d[2][8][4];
#pragma unroll
    for (int mi = 0; mi < 2; mi++)
#pragma unroll
        for (int t = 0; t < 8; t++)
            d[mi][t][0] = d[mi][t][1] = d[mi][t][2] = d[mi][t][3] = 0.f;

    for (int ch = 0; ch < 4; ch++) {
        CP_WAIT0();
        __syncthreads();
        if (ch < 3) issue(ch + 1, ((ch + 1) & 1) ? 4608 : 0,
                                  ((ch + 1) & 1) ? 18432 : 9216);
        mma_block2<8>(sm + ((ch & 1) ? 4608 : 0), 36, 0,
                      sm + ((ch & 1) ? 18432 : 9216), 36, 0,
                      m0, n1, 4, d, g, c);
    }

#pragma unroll
    for (int mi = 0; mi < 2; mi++) {
        int r0 = m0 + mi * 16 + g;
        int gn0 = bb + r0, gn1 = bb + r0 + 8;
#pragma unroll
        for (int nt = 0; nt < 8; nt++) {
            int col = n1 + nt * 8 + 2 * c;
            if (gn0 < N)
                *(float2*)(g_hvw + (size_t)gn0 * 256 + col) =
                    make_float2(d[mi][nt][0], d[mi][nt][1]);
            if (gn1 < N)
                *(float2*)(g_hvw + (size_t)gn1 * 256 + col) =
                    make_float2(d[mi][nt][2], d[mi][nt][3]);
        }
    }
}

// =====================================================================
// K1: logits MLP (hE 256 -> 256 (+hvw init) -> 128 -> 4), tf32 mma
// 64 edges/block, 256 threads, 8 warps (2 m-rows x 4 n-cols), 2 CTAs/SM.
// word offsets: AsA@0(2304) AsB@2304 | WsA@4608(9216) WsB@13824(9216) end 23040
//   H1@0 [64][260]=16640 (aliases dead L1 bufs)
//   W2A@16640(4608) W2B@21248(4608) end 25856
//   H2@0 fp32 [64][132]=8448 (aliases dead H1)
//   misc: bm1s@25856 bm2s@26112 bm3s@26240 wm3s@26244 cids@26756 end 26820
// =====================================================================
#define LG_SMEM (26824 * 4)

__global__ void __launch_bounds__(256, 2) k_logits_mma(
    const float* __restrict__ hE, const int* __restrict__ cid,
    const float* __restrict__ bm1, const float* __restrict__ bm2,
    const float* __restrict__ Wm3, const float* __restrict__ bm3,
    int E)
{
    extern __shared__ uint32_t sm[];
    float* bm1s = (float*)(sm + 25856);
    float* bm2s = (float*)(sm + 26112);
    float* bm3s = (float*)(sm + 26240);
    float* wm3s = (float*)(sm + 26244);   // [k][h], 512
    int*   cids = (int*)(sm + 26756);

    const int tid = threadIdx.x;
    const int w = tid >> 5, lane = tid & 31;
    const int g = lane >> 2, c = lane & 3;
    const int be = blockIdx.x * 64;
    const uint32_t sb = smem_u32(sm);

    const float* gWm1b = g_w + 128;       // Wm1 cols 128..383 (hE part), pitch 384
    const float* gWm2 = g_w + 98304;

    if (tid < 64) cids[tid] = cid[min(be + tid, E - 1)];

    auto issueL1 = [&](int ch, int hsOff, int wsOff) {
#pragma unroll
        for (int rep = 0; rep < 2; rep++) {
            int it = rep * 256 + tid;
            int e = it >> 3, q = it & 7;
            cp16(sb + (hsOff + e * 36 + q * 4) * 4,
                 hE + (size_t)min(be + e, E - 1) * 256 + ch * 32 + q * 4);
        }
#pragma unroll
        for (int rep = 0; rep < 8; rep++) {
            int it = rep * 256 + tid;
            int o = it >> 3, q = it & 7;
            cp16(sb + (wsOff + o * 36 + q * 4) * 4,
                 gWm1b + (size_t)o * 384 + ch * 32 + q * 4);
        }
        CP_COMMIT();
    };
    auto issueW2 = [&](int ch, int wsOff) {
#pragma unroll
        for (int rep = 0; rep < 4; rep++) {
            int it = rep * 256 + tid;
            int o = it >> 3, q = it & 7;
            cp16(sb + (wsOff + o * 36 + q * 4) * 4, gWm2 + (size_t)o * 256 + ch * 32 + q * 4);
        }
        CP_COMMIT();
    };

    issueL1(0, 0, 4608);
    bm1s[tid] = bm1[tid];
    if (tid < 128) bm2s[tid] = bm2[tid];
    if (tid < 4)   bm3s[tid] = bm3[tid];
    wm3s[(tid & 127) * 4 + (tid >> 7)] = Wm3[tid];
    wm3s[((tid + 256) & 127) * 4 + ((tid + 256) >> 7)] = Wm3[tid + 256];
    __syncthreads();   // cids visible

    const int m0 = (w >> 2) * 32;
    const int nc = w & 3;

    // ---- layer 1: K=256 (hE), N=256; acc init = hvw gather ----
    const int n1 = nc * 64;
    float d1[2][8][4];
#pragma unroll
    for (int mi = 0; mi < 2; mi++) {
        int r0 = m0 + mi * 16 + g;
        const float* p0 = g_hvw + (size_t)cids[r0] * 256;
        const float* p1 = g_hvw + (size_t)cids[r0 + 8] * 256;
#pragma unroll
        for (int nt = 0; nt < 8; nt++) {
            int col = n1 + nt * 8 + 2 * c;
            float2 v0 = *(const float2*)(p0 + col);
            float2 v1 = *(const float2*)(p1 + col);
            d1[mi][nt][0] = v0.x; d1[mi][nt][1] = v0.y;
            d1[mi][nt][2] = v1.x; d1[mi][nt][3] = v1.y;
        }
    }

    for (int ch = 0; ch < 8; ch++) {
        CP_WAIT0();
        __syncthreads();
        if (ch < 7) issueL1(ch + 1, ((ch + 1) & 1) ? 2304 : 0,
                                    ((ch + 1) & 1) ? 13824 : 4608);
        mma_block2<8>(sm + ((ch & 1) ? 2304 : 0), 36, 0,
                      sm + ((ch & 1) ? 13824 : 4608), 36, 0,
                      m0, n1, 4, d1, g, c);
    }
    __syncthreads();         // all L1 mma done -> WsA/WsB dead
    issueW2(0, 16640);       // W2A (disjoint from H1 0..16640)

    // epilogue 1 -> H1 @0, pitch 260 (tf32-rounded)
    uint32_t* H1 = sm;
#pragma unroll
    for (int mi = 0; mi < 2; mi++) {
        int r0 = m0 + mi * 16 + g;
#pragma unroll
        for (int nt = 0; nt < 8; nt++) {
            int col = n1 + nt * 8 + 2 * c;
            float b0 = bm1s[col], b1 = bm1s[col + 1];
            uint2 u0, u1;
            u0.x = tf32r(gelu_f(d1[mi][nt][0] + b0));
            u0.y = tf32r(gelu_f(d1[mi][nt][1] + b1));
            u1.x = tf32r(gelu_f(d1[mi][nt][2] + b0));
            u1.y = tf32r(gelu_f(d1[mi][nt][3] + b1));
            *(uint2*)&H1[r0 * 260 + col] = u0;
            *(uint2*)&H1[(r0 + 8) * 260 + col] = u1;
        }
    }

    // ---- layer 2: K=256, N=128 ----
    const int n2 = nc * 32;
    float d2[2][4][4];
#pragma unroll
    for (int mi = 0; mi < 2; mi++)
#pragma unroll
        for (int t = 0; t < 4; t++)
            d2[mi][t][0] = d2[mi][t][1] = d2[mi][t][2] = d2[mi][t][3] = 0.f;

    for (int ch = 0; ch < 8; ch++) {
        CP_WAIT0();
        __syncthreads();   // chunk ch ready + (ch==0) H1 writes visible
        if (ch < 7) issueW2(ch + 1, ((ch + 1) & 1) ? 21248 : 16640);
        mma_block2<4>(H1, 260, ch * 32,
                      sm + ((ch & 1) ? 21248 : 16640), 36, 0,
                      m0, n2, 4, d2, g, c);
    }
    __syncthreads();   // all H1 reads done -> H2 region free

    // epilogue 2 -> H2 @0, pitch 132, plain float
    float* H2 = (float*)sm;
#pragma unroll
    for (int mi = 0; mi < 2; mi++) {
        int r0 = m0 + mi * 16 + g;
#pragma unroll
        for (int nt = 0; nt < 4; nt++) {
            int col = n2 + nt * 8 + 2 * c;
            float b0 = bm2s[col], b1 = bm2s[col + 1];
            float2 v0, v1;
            v0.x = gelu_f(d2[mi][nt][0] + b0);
            v0.y = gelu_f(d2[mi][nt][1] + b1);
            v1.x = gelu_f(d2[mi][nt][2] + b0);
            v1.y = gelu_f(d2[mi][nt][3] + b1);
            *(float2*)&H2[r0 * 132 + col] = v0;
            *(float2*)&H2[(r0 + 8) * 132 + col] = v1;
        }
    }
    __syncthreads();

    // ---- layer 3: K=128, N=4 + segment-max atomics ----
    {
        int e = tid >> 2, h = tid & 3;
        const float4* hr = (const float4*)(H2 + e * 132);
        float s = 0.f;
#pragma unroll
        for (int k4 = 0; k4 < 32; k4++) {
            float4 x = hr[k4];
            s += x.x * wm3s[(k4 * 4 + 0) * 4 + h];
            s += x.y * wm3s[(k4 * 4 + 1) * 4 + h];
            s += x.z * wm3s[(k4 * 4 + 2) * 4 + h];
            s += x.w * wm3s[(k4 * 4 + 3) * 4 + h];
        }
        if (be + e < E) {
            float lg = (s + bm3s[h]) * 0.17677669529663687f;
            g_logits[(size_t)(be + e) * 4 + h] = lg;
            atomicMaxF(&g_segmax[cids[e] * 4 + h], lg);
        }
    }
}

// =====================================================================
// K5: value MLP (256->128->128->128) + attend + scatter
// 64 edges/block, 256 threads, 8 warps (M32 x N32 each), 2 CTAs/SM.
// =====================================================================
#define VL_SMEM (22976 * 4)

__global__ void __launch_bounds__(256, 2) k_value_mma(
    const float* __restrict__ hE, const int* __restrict__ cid,
    const float* __restrict__ bv1, const float* __restrict__ bv2,
    const float* __restrict__ bv3, int E)
{
    extern __shared__ uint32_t sm[];
    uint32_t* H = sm + 13824;   // pitch 132 u32
    float* bv1s = (float*)(sm + 22272);
    float* bv2s = (float*)(sm + 22400);
    float* bv3s = (float*)(sm + 22528);
    float* atts = (float*)(sm + 22656);
    int*   cids = (int*)(sm + 22912);

    const int tid = threadIdx.x;
    const int w = tid >> 5, lane = tid & 31;
    const int g = lane >> 2, c = lane & 3;
    const int be = blockIdx.x * 64;
    const uint32_t sb = smem_u32(sm);

    const float* gWv1 = g_w + 131072;
    const float* gWv2 = g_w + 163840;
    const float* gWv3 = g_w + 180224;

    if (tid < 64) cids[tid] = cid[min(be + tid, E - 1)];
    if (tid < 128) {
        bv1s[tid] = bv1[tid];
        bv2s[tid] = bv2[tid];
        bv3s[tid] = bv3[tid];
    }

    auto issueL1 = [&](int ch, int hsOff, int wsOff) {
#pragma unroll
        for (int rep = 0; rep < 2; rep++) {
            int it = rep * 256 + tid;
            int e = it >> 3, q = it & 7;
            cp16(sb + (hsOff + e * 36 + q * 4) * 4,
                 hE + (size_t)min(be + e, E - 1) * 256 + ch * 32 + q * 4);
        }
#pragma unroll
        for (int rep = 0; rep < 4; rep++) {
            int it = rep * 256 + tid;
            int o = it >> 3, q = it & 7;
            cp16(sb + (wsOff + o * 36 + q * 4) * 4, gWv1 + (size_t)o * 256 + ch * 32 + q * 4);
        }
        CP_COMMIT();
    };
    auto issueW = [&](const float* W, int ch, int wsOff) {
#pragma unroll
        for (int rep = 0; rep < 4; rep++) {
            int it = rep * 256 + tid;
            int o = it >> 3, q = it & 7;
            cp16(sb + (wsOff + o * 36 + q * 4) * 4, W + (size_t)o * 128 + ch * 32 + q * 4);
        }
        CP_COMMIT();
    };

    issueL1(0, 0, 4608);

    const int m0 = (w >> 2) * 32;   // 2 m-rows of 32
    const int n0 = (w & 3) * 32;    // 4 n-cols of 32
    float d[2][4][4];

    // ---------------- layer 1: K=256 ----------------
#pragma unroll
    for (int mi = 0; mi < 2; mi++)
#pragma unroll
        for (int t = 0; t < 4; t++)
            d[mi][t][0] = d[mi][t][1] = d[mi][t][2] = d[mi][t][3] = 0.f;
    for (int ch = 0; ch < 8; ch++) {
        CP_WAIT0();
        __syncthreads();
        if (ch < 7) issueL1(ch + 1, ((ch + 1) & 1) ? 2304 : 0,
                                    ((ch + 1) & 1) ? 9216 : 4608);
        mma_block2<4>(sm + ((ch & 1) ? 2304 : 0), 36, 0,
                      sm + ((ch & 1) ? 9216 : 4608), 36, 0,
                      m0, n0, 4, d, g, c);
    }
    issueW(gWv2, 0, 4608);   // ch7 read 9216 -> 4608 free
    __syncthreads();

    // epilogue 1 -> H (H1v)
#pragma unroll
    for (int mi = 0; mi < 2; mi++) {
        int r0 = m0 + mi * 16 + g;
#pragma unroll
        for (int nt = 0; nt < 4; nt++) {
            int col = n0 + nt * 8 + 2 * c;
            float b0 = bv1s[col], b1 = bv1s[col + 1];
            uint2 u0, u1;
            u0.x = tf32r(gelu_f(d[mi][nt][0] + b0));
            u0.y = tf32r(gelu_f(d[mi][nt][1] + b1));
            u1.x = tf32r(gelu_f(d[mi][nt][2] + b0));
            u1.y = tf32r(gelu_f(d[mi][nt][3] + b1));
            *(uint2*)&H[r0 * 132 + col] = u0;
            *(uint2*)&H[(r0 + 8) * 132 + col] = u1;
        }
    }

    // ---------------- layer 2: K=128 (reads H) ----------------
#pragma unroll
    for (int mi = 0; mi < 2; mi++)
#pragma unroll
        for (int t = 0; t < 4; t++)
            d[mi][t][0] = d[mi][t][1] = d[mi][t][2] = d[mi][t][3] = 0.f;
    for (int ch = 0; ch < 4; ch++) {
        CP_WAIT0();
        __syncthreads();
        if (ch < 3) issueW(gWv2, ch + 1, ((ch + 1) & 1) ? 9216 : 4608);
        mma_block2<4>(H, 132, ch * 32,
                      sm + ((ch & 1) ? 9216 : 4608), 36, 0,
                      m0, n0, 4, d, g, c);
    }
    issueW(gWv3, 0, 4608);   // ch3 read 9216 -> 4608 free
    __syncthreads();         // all H reads done -> may overwrite H

    // epilogue 2 -> H (H2v, aliases H1v)
#pragma unroll
    for (int mi = 0; mi < 2; mi++) {
        int r0 = m0 + mi * 16 + g;
#pragma unroll
        for (int nt = 0; nt < 4; nt++) {
            int col = n0 + nt * 8 + 2 * c;
            float b0 = bv2s[col], b1 = bv2s[col + 1];
            uint2 u0, u1;
            u0.x = tf32r(gelu_f(d[mi][nt][0] + b0));
            u0.y = tf32r(gelu_f(d[mi][nt][1] + b1));
            u1.x = tf32r(gelu_f(d[mi][nt][2] + b0));
            u1.y = tf32r(gelu_f(d[mi][nt][3] + b1));
            *(uint2*)&H[r0 * 132 + col] = u0;
            *(uint2*)&H[(r0 + 8) * 132 + col] = u1;
        }
    }
    // attend weights (g_logits holds ex after k_exsum); visible after next barrier
    {
        int e = tid >> 2, hh = tid & 3;
        int ge = min(be + e, E - 1);
        atts[tid] = g_logits[(size_t)ge * 4 + hh] / g_segsum[cids[e] * 4 + hh];
    }

    // ---------------- layer 3: K=128 (reads H) ----------------
#pragma unroll
    for (int mi = 0; mi < 2; mi++)
#pragma unroll
        for (int t = 0; t < 4; t++)
            d[mi][t][0] = d[mi][t][1] = d[mi][t][2] = d[mi][t][3] = 0.f;
    for (int ch = 0; ch < 4; ch++) {
        CP_WAIT0();
        __syncthreads();
        if (ch < 3) issueW(gWv3, ch + 1, ((ch + 1) & 1) ? 9216 : 4608);
        mma_block2<4>(H, 132, ch * 32,
                      sm + ((ch & 1) ? 9216 : 4608), 36, 0,
                      m0, n0, 4, d, g, c);
    }
    __syncthreads();   // all H reads done -> Fout may overwrite H

    // epilogue 3: (V + b) * attend -> Fout (aliases H), then scatter
    float* Fout = (float*)H;
#pragma unroll
    for (int mi = 0; mi < 2; mi++) {
        int r0 = m0 + mi * 16 + g;
#pragma unroll
        for (int nt = 0; nt < 4; nt++) {
            int col = n0 + nt * 8 + 2 * c;
            int head = col >> 5;
            float b0 = bv3s[col], b1 = bv3s[col + 1];
            float a0 = atts[r0 * 4 + head];
            float a1 = atts[(r0 + 8) * 4 + head];
            float2 v0, v1;
            v0.x = (d[mi][nt][0] + b0) * a0;
            v0.y = (d[mi][nt][1] + b1) * a0;
            v1.x = (d[mi][nt][2] + b0) * a1;
            v1.y = (d[mi][nt][3] + b1) * a1;
            *(float2*)&Fout[r0 * 132 + col] = v0;
            *(float2*)&Fout[(r0 + 8) * 132 + col] = v1;
        }
    }
    __syncthreads();
    for (int it = tid; it < 2048; it += 256) {
        int e = it >> 5, q = it & 31;
        if (be + e < E) {
            float4 v = *(const float4*)&Fout[e * 132 + q * 4];
            red4(g_agg + (size_t)cids[e] * 128 + q * 4, v);
        }
    }
}

// ---------------- exp + segment-sum --------------------------------------------
__global__ void k_exsum(const int* __restrict__ cid, int E) {
    int i = blockIdx.x * blockDim.x + threadIdx.x;
    if (i >= E * 4) return;
    int e = i >> 2, h = i & 3;
    int c = cid[e];
    float ex = expf(g_logits[i] - g_segmax[c * 4 + h]);
    g_logits[i] = ex;
    atomicAdd(&g_segsum[c * 4 + h], ex);
}

// ---------------- K6: out = agg @ Wo^T (fp32 f32x2; exact) --------------------
#define K6_WS   (64 * 132)
#define K6_SMEM ((K6_WS + 128 * 34) * 4)

__global__ void __launch_bounds__(256) k_out(const float* __restrict__ Wo,
                                             float* __restrict__ out, int N)
{
    extern __shared__ float smf[];
    float* xs = smf;
    float* ws = smf + K6_WS;

    const int tid = threadIdx.x;
    const int be  = blockIdx.x * 64;
    const int oo  = tid & 31;
    const int eo  = tid >> 5;

    for (int idx = tid; idx < 64 * 32; idx += 256) {
        int e = idx >> 5, f = idx & 31;
        int gn = min(be + e, N - 1);
        *(float4*)(xs + e * 132 + f * 4) = ((const float4*)g_agg)[(size_t)gn * 32 + f];
    }
    __syncthreads();

    unsigned long long accB[32];
#pragma unroll
    for (int t = 0; t < 32; t++) accB[t] = 0ULL;
    for (int kt = 0; kt < 128; kt += 32) {
        for (int idx = tid; idx < 128 * 16; idx += 256) {
            int o = idx >> 4, q = idx & 15;
            *(float2*)(ws + o * 34 + q * 2) =
                *(const float2*)(Wo + o * 128 + kt + q * 2);
        }
        __syncthreads();
#pragma unroll 4
        for (int kk = 0; kk < 32; kk += 2) {
            unsigned long long x2[8];
#pragma unroll
            for (int i = 0; i < 8; i++)
                x2[i] = *(const unsigned long long*)(xs + (eo * 8 + i) * 132 + kt + kk);
#pragma unroll
            for (int j = 0; j < 4; j++) {
                unsigned long long w2 =
                    *(const unsigned long long*)(ws + (oo + 32 * j) * 34 + kk);
#pragma unroll
                for (int i = 0; i < 8; i++) fma2(accB[i * 4 + j], x2[i], w2);
            }
        }
        __syncthreads();
    }
#pragma unroll
    for (int j = 0; j < 4; j++) {
#pragma unroll
        for (int i = 0; i < 8; i++) {
            int gn = be + eo * 8 + i;
            if (gn < N)
                out[(size_t)gn * 128 + oo + 32 * j] = f2sum(accB[i * 4 + j]);
        }
    }
}

// ---------------- launch -------------------------------------------------------
extern "C" void kernel_launch(void* const* d_in, const int* in_sizes, int n_in,
                              void* d_out, int out_size)
{
    const float* hV  = (const float*)d_in[0];
    const float* hE  = (const float*)d_in[1];
    const int*   cid = (const int*)  d_in[2];
    const float* Wv1 = (const float*)d_in[3];
    const float* bv1 = (const float*)d_in[4];
    const float* Wv2 = (const float*)d_in[5];
    const float* bv2 = (const float*)d_in[6];
    const float* Wv3 = (const float*)d_in[7];
    const float* bv3 = (const float*)d_in[8];
    const float* Wm1 = (const float*)d_in[9];
    const float* bm1 = (const float*)d_in[10];
    const float* Wm2 = (const float*)d_in[11];
    const float* bm2 = (const float*)d_in[12];
    const float* Wm3 = (const float*)d_in[13];
    const float* bm3 = (const float*)d_in[14];
    const float* Wo  = (const float*)d_in[15];

    int N = in_sizes[0] / 128;
    int E = in_sizes[2];

    cudaFuncSetAttribute(k_hvw,        cudaFuncAttributeMaxDynamicSharedMemorySize, HV_SMEM);
    cudaFuncSetAttribute(k_logits_mma, cudaFuncAttributeMaxDynamicSharedMemorySize, LG_SMEM);
    cudaFuncSetAttribute(k_value_mma,  cudaFuncAttributeMaxDynamicSharedMemorySize, VL_SMEM);
    cudaFuncSetAttribute(k_out,        cudaFuncAttributeMaxDynamicSharedMemorySize, K6_SMEM);

    int eb2 = (E + 63) / 64;
    int nb = (N + 63) / 64;
    int hb = (N + 127) / 128;

    k_init<<<(N * 128 + 255) / 256, 256>>>(N);
    k_prep<<<768, 256>>>(Wm1, Wm2, Wv1, Wv2, Wv3);
    k_hvw<<<hb, 512, HV_SMEM>>>(hV, N);
    k_logits_mma<<<eb2, 256, LG_SMEM>>>(hE, cid, bm1, bm2, Wm3, bm3, E);
    k_exsum<<<(E * 4 + 255) / 256, 256>>>(cid, E);
    k_value_mma<<<eb2, 256, VL_SMEM>>>(hE, cid, bv1, bv2, bv3, E);
    k_out<<<nb, 256, K6_SMEM>>>(Wo, (float*)d_out, N);
}

// round 12
// speedup vs baseline: 1.0535x; 1.0535x over previous
#include <cuda_runtime.h>
#include <math.h>
#include <stdint.h>

#define EMAX 800000
#define NMAX 50000

// ---------------- scratch ----------------------------------------------------
__device__ float g_logits[EMAX * 4];   // ex (un-shifted softmax numerator)
__device__ float g_segsum[NMAX * 4];
__device__ float g_agg[NMAX * 128];
__device__ float g_hvw[NMAX * 256];    // hV @ Wm1[:, :128]^T  per node
// pre-rounded tf32 weights: Wm1(98304) Wm2(32768) Wv1(32768) Wv2(16384)
//                           Wv3(16384) Wo(16384)
__device__ __align__(16) float g_w[212992];

// ---------------- helpers ------------------------------------------------------
__device__ __forceinline__ float gelu_f(float x) {
    return 0.5f * x * (1.0f + erff(x * 0.7071067811865476f));
}
__device__ __forceinline__ void red4(float* p, float4 v) {
    asm volatile("red.global.add.v4.f32 [%0], {%1,%2,%3,%4};"
                 :: "l"(p), "f"(v.x), "f"(v.y), "f"(v.z), "f"(v.w) : "memory");
}
__device__ __forceinline__ uint32_t tf32r(float f) {
    uint32_t r;
    asm("cvt.rna.tf32.f32 %0, %1;" : "=r"(r) : "f"(f));
    return r;
}
__device__ __forceinline__ uint32_t smem_u32(const void* p) {
    uint32_t a;
    asm("{ .reg .u64 t; cvta.to.shared.u64 t, %1; cvt.u32.u64 %0, t; }"
        : "=r"(a) : "l"(p));
    return a;
}
__device__ __forceinline__ void cp16(uint32_t dst, const void* src) {
    asm volatile("cp.async.ca.shared.global [%0], [%1], 16;" :: "r"(dst), "l"(src));
}
#define CP_COMMIT() asm volatile("cp.async.commit_group;" ::: "memory")
#define CP_WAIT0()  asm volatile("cp.async.wait_group 0;" ::: "memory")

// Warp MMA, 2 m-tiles (M32) x NT n-tiles. A[m][k] pitch ap u32 (tf32 bits);
// B[n][k] pitch bp u32. D covers rows [m0,m0+32), cols [n0, n0+8*NT).
template<int NT>
__device__ __forceinline__ void mma_block2(
    const uint32_t* __restrict__ A, int ap, int ka,
    const uint32_t* __restrict__ B, int bp, int kb,
    int m0, int n0, int ksteps, float d[2][NT][4], int g, int c)
{
    for (int ks = 0; ks < ksteps; ks++) {
        uint32_t a[2][4];
#pragma unroll
        for (int mi = 0; mi < 2; mi++) {
            const uint32_t* Ar = A + (m0 + mi * 16 + g) * ap + ka + ks * 8 + c;
            a[mi][0] = Ar[0];
            a[mi][2] = Ar[4];
            a[mi][1] = Ar[8 * ap];
            a[mi][3] = Ar[8 * ap + 4];
        }
        const uint32_t* Bb = B + kb + ks * 8 + c + (n0 + g) * bp;
#pragma unroll
        for (int nt = 0; nt < NT; nt++) {
            uint32_t b0 = Bb[nt * 8 * bp];
            uint32_t b1 = Bb[nt * 8 * bp + 4];
#pragma unroll
            for (int mi = 0; mi < 2; mi++) {
                asm volatile(
                    "mma.sync.aligned.m16n8k8.row.col.f32.tf32.tf32.f32 "
                    "{%0,%1,%2,%3}, {%4,%5,%6,%7}, {%8,%9}, {%0,%1,%2,%3};"
                    : "+f"(d[mi][nt][0]), "+f"(d[mi][nt][1]),
                      "+f"(d[mi][nt][2]), "+f"(d[mi][nt][3])
                    : "r"(a[mi][0]), "r"(a[mi][1]), "r"(a[mi][2]), "r"(a[mi][3]),
                      "r"(b0), "r"(b1));
            }
        }
    }
}

// ---------------- init / weight prep ------------------------------------------
__global__ void k_init(int N) {
    int i = blockIdx.x * blockDim.x + threadIdx.x;
    if (i < N * 128) g_agg[i] = 0.0f;
    if (i < N * 4) g_segsum[i] = 0.0f;
}

__global__ void k_prep(const float* __restrict__ Wm1, const float* __restrict__ Wm2,
                       const float* __restrict__ Wv1, const float* __restrict__ Wv2,
                       const float* __restrict__ Wv3, const float* __restrict__ Wo) {
    int i = blockIdx.x * 256 + threadIdx.x;
    float v;
    if (i < 98304)       v = Wm1[i];
    else if (i < 131072) v = Wm2[i - 98304];
    else if (i < 163840) v = Wv1[i - 131072];
    else if (i < 180224) v = Wv2[i - 163840];
    else if (i < 196608) v = Wv3[i - 180224];
    else                 v = Wo[i - 196608];
    g_w[i] = __uint_as_float(tf32r(v));
}

// =====================================================================
// K0: g_hvw[n][0..255] = hV[n] @ Wm1[:, :128]^T   (tf32 mma)
// =====================================================================
#define HV_SMEM (27648 * 4)

__global__ void __launch_bounds__(512, 1) k_hvw(const float* __restrict__ hV, int N)
{
    extern __shared__ uint32_t sm[];
    const int tid = threadIdx.x;
    const int w = tid >> 5, lane = tid & 31;
    const int g = lane >> 2, c = lane & 3;
    const int bb = blockIdx.x * 128;
    const uint32_t sb = smem_u32(sm);
    const float* gWm1 = g_w;

    auto issue = [&](int ch, int hsOff, int wsOff) {
#pragma unroll
        for (int rep = 0; rep < 2; rep++) {
            int it = rep * 512 + tid;
            int e = it >> 3, q = it & 7;
            cp16(sb + (hsOff + e * 36 + q * 4) * 4,
                 hV + (size_t)min(bb + e, N - 1) * 128 + ch * 32 + q * 4);
        }
#pragma unroll
        for (int rep = 0; rep < 4; rep++) {
            int it = rep * 512 + tid;
            int o = it >> 3, q = it & 7;
            cp16(sb + (wsOff + o * 36 + q * 4) * 4,
                 gWm1 + (size_t)o * 384 + ch * 32 + q * 4);
        }
        CP_COMMIT();
    };

    issue(0, 0, 9216);

    const int m0 = (w >> 2) * 32;
    const int n1 = (w & 3) * 64;
    float d[2][8][4];
#pragma unroll
    for (int mi = 0; mi < 2; mi++)
#pragma unroll
        for (int t = 0; t < 8; t++)
            d[mi][t][0] = d[mi][t][1] = d[mi][t][2] = d[mi][t][3] = 0.f;

    for (int ch = 0; ch < 4; ch++) {
        CP_WAIT0();
        __syncthreads();
        if (ch < 3) issue(ch + 1, ((ch + 1) & 1) ? 4608 : 0,
                                  ((ch + 1) & 1) ? 18432 : 9216);
        mma_block2<8>(sm + ((ch & 1) ? 4608 : 0), 36, 0,
                      sm + ((ch & 1) ? 18432 : 9216), 36, 0,
                      m0, n1, 4, d, g, c);
    }

#pragma unroll
    for (int mi = 0; mi < 2; mi++) {
        int r0 = m0 + mi * 16 + g;
        int gn0 = bb + r0, gn1 = bb + r0 + 8;
#pragma unroll
        for (int nt = 0; nt < 8; nt++) {
            int col = n1 + nt * 8 + 2 * c;
            if (gn0 < N)
                *(float2*)(g_hvw + (size_t)gn0 * 256 + col) =
                    make_float2(d[mi][nt][0], d[mi][nt][1]);
            if (gn1 < N)
                *(float2*)(g_hvw + (size_t)gn1 * 256 + col) =
                    make_float2(d[mi][nt][2], d[mi][nt][3]);
        }
    }
}

// =====================================================================
// K1: logits MLP (hE 256 -> 256 (+hvw init) -> 128 -> 4) + exp + segsum
// 128 edges/block, 512 threads (R10 config).
// =====================================================================
#define LG_SMEM (43536 * 4)

__global__ void __launch_bounds__(512, 1) k_logits_mma(
    const float* __restrict__ hE, const int* __restrict__ cid,
    const float* __restrict__ bm1, const float* __restrict__ bm2,
    const float* __restrict__ Wm3, const float* __restrict__ bm3,
    int E)
{
    extern __shared__ uint32_t sm[];
    float* bm1s = (float*)(sm + 42496);
    float* bm2s = (float*)(sm + 42752);
    float* bm3s = (float*)(sm + 42880);
    float* wm3s = (float*)(sm + 42896);   // [k][h], 512
    int*   cids = (int*)(sm + 43408);

    const int tid = threadIdx.x;
    const int w = tid >> 5, lane = tid & 31;
    const int g = lane >> 2, c = lane & 3;
    const int be = blockIdx.x * 128;
    const uint32_t sb = smem_u32(sm);

    const float* gWm1b = g_w + 128;       // Wm1 cols 128..383 (hE part), pitch 384
    const float* gWm2 = g_w + 98304;

    if (tid < 128) cids[tid] = cid[min(be + tid, E - 1)];

    auto issueL1 = [&](int ch, int hsOff, int wsOff) {
#pragma unroll
        for (int rep = 0; rep < 2; rep++) {
            int it = rep * 512 + tid;
            int e = it >> 3, q = it & 7;
            cp16(sb + (hsOff + e * 36 + q * 4) * 4,
                 hE + (size_t)min(be + e, E - 1) * 256 + ch * 32 + q * 4);
        }
#pragma unroll
        for (int rep = 0; rep < 4; rep++) {
            int it = rep * 512 + tid;
            int o = it >> 3, q = it & 7;
            cp16(sb + (wsOff + o * 36 + q * 4) * 4,
                 gWm1b + (size_t)o * 384 + ch * 32 + q * 4);
        }
        CP_COMMIT();
    };
    auto issueW2 = [&](int ch, int wsOff) {
#pragma unroll
        for (int rep = 0; rep < 2; rep++) {
            int it = rep * 512 + tid;
            int o = it >> 3, q = it & 7;
            cp16(sb + (wsOff + o * 36 + q * 4) * 4, gWm2 + (size_t)o * 256 + ch * 32 + q * 4);
        }
        CP_COMMIT();
    };

    issueL1(0, 0, 9216);
    if (tid < 256) bm1s[tid] = bm1[tid];
    if (tid < 128) bm2s[tid] = bm2[tid];
    if (tid < 4)   bm3s[tid] = bm3[tid];
    wm3s[(tid & 127) * 4 + (tid >> 7)] = Wm3[tid];
    __syncthreads();   // cids visible

    const int m0 = (w >> 2) * 32;
    const int nc = w & 3;

    // ---- layer 1: K=256 (hE), N=256; acc init = hvw gather ----
    const int n1 = nc * 64;
    float d1[2][8][4];
#pragma unroll
    for (int mi = 0; mi < 2; mi++) {
        int r0 = m0 + mi * 16 + g;
        const float* p0 = g_hvw + (size_t)cids[r0] * 256;
        const float* p1 = g_hvw + (size_t)cids[r0 + 8] * 256;
#pragma unroll
        for (int nt = 0; nt < 8; nt++) {
            int col = n1 + nt * 8 + 2 * c;
            float2 v0 = *(const float2*)(p0 + col);
            float2 v1 = *(const float2*)(p1 + col);
            d1[mi][nt][0] = v0.x; d1[mi][nt][1] = v0.y;
            d1[mi][nt][2] = v1.x; d1[mi][nt][3] = v1.y;
        }
    }

    for (int ch = 0; ch < 8; ch++) {
        CP_WAIT0();
        __syncthreads();
        if (ch < 7) issueL1(ch + 1, ((ch + 1) & 1) ? 4608 : 0,
                                    ((ch + 1) & 1) ? 18432 : 9216);
        mma_block2<8>(sm + ((ch & 1) ? 4608 : 0), 36, 0,
                      sm + ((ch & 1) ? 18432 : 9216), 36, 0,
                      m0, n1, 4, d1, g, c);
    }
    issueW2(0, 33280);
    __syncthreads();

    // epilogue 1 -> H1 @0, pitch 260 (tf32-rounded)
    uint32_t* H1 = sm;
#pragma unroll
    for (int mi = 0; mi < 2; mi++) {
        int r0 = m0 + mi * 16 + g;
#pragma unroll
        for (int nt = 0; nt < 8; nt++) {
            int col = n1 + nt * 8 + 2 * c;
            float b0 = bm1s[col], b1 = bm1s[col + 1];
            uint2 u0, u1;
            u0.x = tf32r(gelu_f(d1[mi][nt][0] + b0));
            u0.y = tf32r(gelu_f(d1[mi][nt][1] + b1));
            u1.x = tf32r(gelu_f(d1[mi][nt][2] + b0));
            u1.y = tf32r(gelu_f(d1[mi][nt][3] + b1));
            *(uint2*)&H1[r0 * 260 + col] = u0;
            *(uint2*)&H1[(r0 + 8) * 260 + col] = u1;
        }
    }

    // ---- layer 2: K=256, N=128 ----
    const int n2 = nc * 32;
    float d2[2][4][4];
#pragma unroll
    for (int mi = 0; mi < 2; mi++)
#pragma unroll
        for (int t = 0; t < 4; t++)
            d2[mi][t][0] = d2[mi][t][1] = d2[mi][t][2] = d2[mi][t][3] = 0.f;

    for (int ch = 0; ch < 8; ch++) {
        CP_WAIT0();
        __syncthreads();
        if (ch < 7) issueW2(ch + 1, ((ch + 1) & 1) ? 37888 : 33280);
        mma_block2<4>(H1, 260, ch * 32,
                      sm + ((ch & 1) ? 37888 : 33280), 36, 0,
                      m0, n2, 4, d2, g, c);
    }
    __syncthreads();

    // epilogue 2 -> H2 @0, pitch 132, plain float
    float* H2 = (float*)sm;
#pragma unroll
    for (int mi = 0; mi < 2; mi++) {
        int r0 = m0 + mi * 16 + g;
#pragma unroll
        for (int nt = 0; nt < 4; nt++) {
            int col = n2 + nt * 8 + 2 * c;
            float b0 = bm2s[col], b1 = bm2s[col + 1];
            float2 v0, v1;
            v0.x = gelu_f(d2[mi][nt][0] + b0);
            v0.y = gelu_f(d2[mi][nt][1] + b1);
            v1.x = gelu_f(d2[mi][nt][2] + b0);
            v1.y = gelu_f(d2[mi][nt][3] + b1);
            *(float2*)&H2[r0 * 132 + col] = v0;
            *(float2*)&H2[(r0 + 8) * 132 + col] = v1;
        }
    }
    __syncthreads();

    // ---- layer 3: K=128, N=4; ex = exp(logit) (shift-free softmax) + segsum ----
    {
        int e = tid >> 2, h = tid & 3;
        const float4* hr = (const float4*)(H2 + e * 132);
        float s = 0.f;
#pragma unroll
        for (int k4 = 0; k4 < 32; k4++) {
            float4 x = hr[k4];
            s += x.x * wm3s[(k4 * 4 + 0) * 4 + h];
            s += x.y * wm3s[(k4 * 4 + 1) * 4 + h];
            s += x.z * wm3s[(k4 * 4 + 2) * 4 + h];
            s += x.w * wm3s[(k4 * 4 + 3) * 4 + h];
        }
        if (be + e < E) {
            float ex = expf((s + bm3s[h]) * 0.17677669529663687f);
            g_logits[(size_t)(be + e) * 4 + h] = ex;
            atomicAdd(&g_segsum[cids[e] * 4 + h], ex);
        }
    }
}

// =====================================================================
// K5: value MLP (256->128->128->128) + attend + scatter (R10 config)
// 64 edges/block, 256 threads, 8 warps (M32 x N32 each), 2 CTAs/SM.
// =====================================================================
#define VL_SMEM (22976 * 4)

__global__ void __launch_bounds__(256, 2) k_value_mma(
    const float* __restrict__ hE, const int* __restrict__ cid,
    const float* __restrict__ bv1, const float* __restrict__ bv2,
    const float* __restrict__ bv3, int E)
{
    extern __shared__ uint32_t sm[];
    uint32_t* H = sm + 13824;   // pitch 132 u32
    float* bv1s = (float*)(sm + 22272);
    float* bv2s = (float*)(sm + 22400);
    float* bv3s = (float*)(sm + 22528);
    float* atts = (float*)(sm + 22656);
    int*   cids = (int*)(sm + 22912);

    const int tid = threadIdx.x;
    const int w = tid >> 5, lane = tid & 31;
    const int g = lane >> 2, c = lane & 3;
    const int be = blockIdx.x * 64;
    const uint32_t sb = smem_u32(sm);

    const float* gWv1 = g_w + 131072;
    const float* gWv2 = g_w + 163840;
    const float* gWv3 = g_w + 180224;

    if (tid < 64) cids[tid] = cid[min(be + tid, E - 1)];
    if (tid < 128) {
        bv1s[tid] = bv1[tid];
        bv2s[tid] = bv2[tid];
        bv3s[tid] = bv3[tid];
    }

    auto issueL1 = [&](int ch, int hsOff, int wsOff) {
#pragma unroll
        for (int rep = 0; rep < 2; rep++) {
            int it = rep * 256 + tid;
            int e = it >> 3, q = it & 7;
            cp16(sb + (hsOff + e * 36 + q * 4) * 4,
                 hE + (size_t)min(be + e, E - 1) * 256 + ch * 32 + q * 4);
        }
#pragma unroll
        for (int rep = 0; rep < 4; rep++) {
            int it = rep * 256 + tid;
            int o = it >> 3, q = it & 7;
            cp16(sb + (wsOff + o * 36 + q * 4) * 4, gWv1 + (size_t)o * 256 + ch * 32 + q * 4);
        }
        CP_COMMIT();
    };
    auto issueW = [&](const float* W, int ch, int wsOff) {
#pragma unroll
        for (int rep = 0; rep < 4; rep++) {
            int it = rep * 256 + tid;
            int o = it >> 3, q = it & 7;
            cp16(sb + (wsOff + o * 36 + q * 4) * 4, W + (size_t)o * 128 + ch * 32 + q * 4);
        }
        CP_COMMIT();
    };

    issueL1(0, 0, 4608);

    const int m0 = (w >> 2) * 32;   // 2 m-rows of 32
    const int n0 = (w & 3) * 32;    // 4 n-cols of 32
    float d[2][4][4];

    // ---------------- layer 1: K=256 ----------------
#pragma unroll
    for (int mi = 0; mi < 2; mi++)
#pragma unroll
        for (int t = 0; t < 4; t++)
            d[mi][t][0] = d[mi][t][1] = d[mi][t][2] = d[mi][t][3] = 0.f;
    for (int ch = 0; ch < 8; ch++) {
        CP_WAIT0();
        __syncthreads();
        if (ch < 7) issueL1(ch + 1, ((ch + 1) & 1) ? 2304 : 0,
                                    ((ch + 1) & 1) ? 9216 : 4608);
        mma_block2<4>(sm + ((ch & 1) ? 2304 : 0), 36, 0,
                      sm + ((ch & 1) ? 9216 : 4608), 36, 0,
                      m0, n0, 4, d, g, c);
    }
    issueW(gWv2, 0, 4608);   // ch7 read 9216 -> 4608 free
    __syncthreads();

    // epilogue 1 -> H (H1v)
#pragma unroll
    for (int mi = 0; mi < 2; mi++) {
        int r0 = m0 + mi * 16 + g;
#pragma unroll
        for (int nt = 0; nt < 4; nt++) {
            int col = n0 + nt * 8 + 2 * c;
            float b0 = bv1s[col], b1 = bv1s[col + 1];
            uint2 u0, u1;
            u0.x = tf32r(gelu_f(d[mi][nt][0] + b0));
            u0.y = tf32r(gelu_f(d[mi][nt][1] + b1));
            u1.x = tf32r(gelu_f(d[mi][nt][2] + b0));
            u1.y = tf32r(gelu_f(d[mi][nt][3] + b1));
            *(uint2*)&H[r0 * 132 + col] = u0;
            *(uint2*)&H[(r0 + 8) * 132 + col] = u1;
        }
    }

    // ---------------- layer 2: K=128 (reads H) ----------------
#pragma unroll
    for (int mi = 0; mi < 2; mi++)
#pragma unroll
        for (int t = 0; t < 4; t++)
            d[mi][t][0] = d[mi][t][1] = d[mi][t][2] = d[mi][t][3] = 0.f;
    for (int ch = 0; ch < 4; ch++) {
        CP_WAIT0();
        __syncthreads();
        if (ch < 3) issueW(gWv2, ch + 1, ((ch + 1) & 1) ? 9216 : 4608);
        mma_block2<4>(H, 132, ch * 32,
                      sm + ((ch & 1) ? 9216 : 4608), 36, 0,
                      m0, n0, 4, d, g, c);
    }
    issueW(gWv3, 0, 4608);   // ch3 read 9216 -> 4608 free
    __syncthreads();         // all H reads done -> may overwrite H

    // epilogue 2 -> H (H2v, aliases H1v)
#pragma unroll
    for (int mi = 0; mi < 2; mi++) {
        int r0 = m0 + mi * 16 + g;
#pragma unroll
        for (int nt = 0; nt < 4; nt++) {
            int col = n0 + nt * 8 + 2 * c;
            float b0 = bv2s[col], b1 = bv2s[col + 1];
            uint2 u0, u1;
            u0.x = tf32r(gelu_f(d[mi][nt][0] + b0));
            u0.y = tf32r(gelu_f(d[mi][nt][1] + b1));
            u1.x = tf32r(gelu_f(d[mi][nt][2] + b0));
            u1.y = tf32r(gelu_f(d[mi][nt][3] + b1));
            *(uint2*)&H[r0 * 132 + col] = u0;
            *(uint2*)&H[(r0 + 8) * 132 + col] = u1;
        }
    }
    // attend weights (g_logits holds ex); visible after next barrier
    {
        int e = tid >> 2, hh = tid & 3;
        int ge = min(be + e, E - 1);
        atts[tid] = g_logits[(size_t)ge * 4 + hh] / g_segsum[cids[e] * 4 + hh];
    }

    // ---------------- layer 3: K=128 (reads H) ----------------
#pragma unroll
    for (int mi = 0; mi < 2; mi++)
#pragma unroll
        for (int t = 0; t < 4; t++)
            d[mi][t][0] = d[mi][t][1] = d[mi][t][2] = d[mi][t][3] = 0.f;
    for (int ch = 0; ch < 4; ch++) {
        CP_WAIT0();
        __syncthreads();
        if (ch < 3) issueW(gWv3, ch + 1, ((ch + 1) & 1) ? 9216 : 4608);
        mma_block2<4>(H, 132, ch * 32,
                      sm + ((ch & 1) ? 9216 : 4608), 36, 0,
                      m0, n0, 4, d, g, c);
    }
    __syncthreads();   // all H reads done -> Fout may overwrite H

    // epilogue 3: (V + b) * attend -> Fout (aliases H), then scatter
    float* Fout = (float*)H;
#pragma unroll
    for (int mi = 0; mi < 2; mi++) {
        int r0 = m0 + mi * 16 + g;
#pragma unroll
        for (int nt = 0; nt < 4; nt++) {
            int col = n0 + nt * 8 + 2 * c;
            int head = col >> 5;
            float b0 = bv3s[col], b1 = bv3s[col + 1];
            float a0 = atts[r0 * 4 + head];
            float a1 = atts[(r0 + 8) * 4 + head];
            float2 v0, v1;
            v0.x = (d[mi][nt][0] + b0) * a0;
            v0.y = (d[mi][nt][1] + b1) * a0;
            v1.x = (d[mi][nt][2] + b0) * a1;
            v1.y = (d[mi][nt][3] + b1) * a1;
            *(float2*)&Fout[r0 * 132 + col] = v0;
            *(float2*)&Fout[(r0 + 8) * 132 + col] = v1;
        }
    }
    __syncthreads();
    for (int it = tid; it < 2048; it += 256) {
        int e = it >> 5, q = it & 31;
        if (be + e < E) {
            float4 v = *(const float4*)&Fout[e * 132 + q * 4];
            red4(g_agg + (size_t)cids[e] * 128 + q * 4, v);
        }
    }
}

// =====================================================================
// K6: out = agg @ Wo^T via tf32 mma. 64 nodes/block, 256 threads, 2 CTAs/SM.
// smem: xs[64][132]@0 (8448 w), ws[128][132]@8448 (16896 w) -> 101 KB
// =====================================================================
#define KO_SMEM (25344 * 4)

__global__ void __launch_bounds__(256, 2) k_out(float* __restrict__ out, int N)
{
    extern __shared__ uint32_t sm[];
    uint32_t* xs = sm;
    uint32_t* ws = sm + 8448;

    const int tid = threadIdx.x;
    const int w = tid >> 5, lane = tid & 31;
    const int g = lane >> 2, c = lane & 3;
    const int be = blockIdx.x * 64;
    const float* gWo = g_w + 196608;   // tf32-rounded [128][128]

    // stage x (agg rows, tf32-rounded) and Wo
    for (int it = tid; it < 2048; it += 256) {
        int e = it >> 5, q = it & 31;
        int gn = min(be + e, N - 1);
        float4 v = ((const float4*)g_agg)[(size_t)gn * 32 + q];
        uint4 u;
        u.x = tf32r(v.x); u.y = tf32r(v.y); u.z = tf32r(v.z); u.w = tf32r(v.w);
        *(uint4*)&xs[e * 132 + q * 4] = u;
    }
    for (int it = tid; it < 4096; it += 256) {
        int o = it >> 5, q = it & 31;
        *(uint4*)&ws[o * 132 + q * 4] = *(const uint4*)(gWo + (size_t)o * 128 + q * 4);
    }
    __syncthreads();

    const int m0 = (w >> 2) * 32;
    const int n0 = (w & 3) * 32;
    float d[2][4][4];
#pragma unroll
    for (int mi = 0; mi < 2; mi++)
#pragma unroll
        for (int t = 0; t < 4; t++)
            d[mi][t][0] = d[mi][t][1] = d[mi][t][2] = d[mi][t][3] = 0.f;

    mma_block2<4>(xs, 132, 0, ws, 132, 0, m0, n0, 16, d, g, c);

#pragma unroll
    for (int mi = 0; mi < 2; mi++) {
        int r0 = m0 + mi * 16 + g;
        int gn0 = be + r0, gn1 = be + r0 + 8;
#pragma unroll
        for (int nt = 0; nt < 4; nt++) {
            int col = n0 + nt * 8 + 2 * c;
            if (gn0 < N)
                *(float2*)(out + (size_t)gn0 * 128 + col) =
                    make_float2(d[mi][nt][0], d[mi][nt][1]);
            if (gn1 < N)
                *(float2*)(out + (size_t)gn1 * 128 + col) =
                    make_float2(d[mi][nt][2], d[mi][nt][3]);
        }
    }
}

// ---------------- launch -------------------------------------------------------
extern "C" void kernel_launch(void* const* d_in, const int* in_sizes, int n_in,
                              void* d_out, int out_size)
{
    const float* hV  = (const float*)d_in[0];
    const float* hE  = (const float*)d_in[1];
    const int*   cid = (const int*)  d_in[2];
    const float* Wv1 = (const float*)d_in[3];
    const float* bv1 = (const float*)d_in[4];
    const float* Wv2 = (const float*)d_in[5];
    const float* bv2 = (const float*)d_in[6];
    const float* Wv3 = (const float*)d_in[7];
    const float* bv3 = (const float*)d_in[8];
    const float* Wm1 = (const float*)d_in[9];
    const float* bm1 = (const float*)d_in[10];
    const float* Wm2 = (const float*)d_in[11];
    const float* bm2 = (const float*)d_in[12];
    const float* Wm3 = (const float*)d_in[13];
    const float* bm3 = (const float*)d_in[14];
    const float* Wo  = (const float*)d_in[15];

    int N = in_sizes[0] / 128;
    int E = in_sizes[2];

    cudaFuncSetAttribute(k_hvw,        cudaFuncAttributeMaxDynamicSharedMemorySize, HV_SMEM);
    cudaFuncSetAttribute(k_logits_mma, cudaFuncAttributeMaxDynamicSharedMemorySize, LG_SMEM);
    cudaFuncSetAttribute(k_value_mma,  cudaFuncAttributeMaxDynamicSharedMemorySize, VL_SMEM);
    cudaFuncSetAttribute(k_out,        cudaFuncAttributeMaxDynamicSharedMemorySize, KO_SMEM);

    int eb  = (E + 127) / 128;
    int eb2 = (E + 63) / 64;
    int nb  = (N + 63) / 64;
    int hb  = (N + 127) / 128;

    k_init<<<(N * 128 + 255) / 256, 256>>>(N);
    k_prep<<<832, 256>>>(Wm1, Wm2, Wv1, Wv2, Wv3, Wo);
    k_hvw<<<hb, 512, HV_SMEM>>>(hV, N);
    k_logits_mma<<<eb, 512, LG_SMEM>>>(hE, cid, bm1, bm2, Wm3, bm3, E);
    k_value_mma<<<eb2, 256, VL_SMEM>>>(hE, cid, bv1, bv2, bv3, E);
    k_out<<<nb, 256, KO_SMEM>>>((float*)d_out, N);
}